// round 6
// baseline (speedup 1.0000x reference)
#include <cuda_runtime.h>
#include <cstdint>
#include <cfloat>

#define NH    218
#define NHP   224        // padded h stride (16B-aligned rows)
#define NSUB  47524      // 218*218
#define NROWS 64         // B * C_OUT * C_IN
#define QG    55         // quad-groups per h1 row (55*4 = 220 >= 218)
#define TPB   220        // 4 h1 rows * 55 quad-groups

// ---------------- device globals (no allocations allowed) ----------------
__device__ __align__(16) float g_Wn[32 * 24 * 16];          // -2*Kstruct, [oi][p][c]
__device__ float g_c2[32];                                   // ||K||^2+||R||^2+||C||^2
__device__ __align__(16) float g_rpn[2 * 32 * 24 * NHP];     // rpart [b][oi][p][h1]
__device__ __align__(16) float g_cpn[2 * 32 * 24 * NHP];     // cpart [b][oi][p][h2]
__device__ float g_pmax[NROWS][NH];
__device__ float g_psum[NROWS][NH];
__device__ float g_fac[NROWS][NH];
__device__ __align__(16) float g_sims[(size_t)NROWS * NSUB]; // m, then exp(m - blkmax)

__constant__ unsigned char c_P[24][4] = {
  {0,1,2,3},{0,1,3,2},{0,2,1,3},{0,2,3,1},{0,3,1,2},{0,3,2,1},
  {1,0,2,3},{1,0,3,2},{1,2,0,3},{1,2,3,0},{1,3,0,2},{1,3,2,0},
  {2,0,1,3},{2,0,3,1},{2,1,0,3},{2,1,3,0},{2,3,0,1},{2,3,1,0},
  {3,0,1,2},{3,0,2,1},{3,1,0,2},{3,1,2,0},{3,2,0,1},{3,2,1,0}
};

// ---------------- packed f32x2 helpers -----------------------------------
__device__ __forceinline__ unsigned long long dup2(float f) {
    unsigned long long r;
    asm("mov.b64 %0, {%1, %1};" : "=l"(r) : "f"(f));
    return r;
}
__device__ __forceinline__ unsigned long long pk2(float a, float b) {
    unsigned long long r;
    asm("mov.b64 %0, {%1, %2};" : "=l"(r) : "f"(a), "f"(b));
    return r;
}
__device__ __forceinline__ unsigned long long add2(unsigned long long a, unsigned long long b) {
    unsigned long long r;
    asm("add.rn.f32x2 %0, %1, %2;" : "=l"(r) : "l"(a), "l"(b));
    return r;
}
#define FMA2(acc, x, w) asm("fma.rn.f32x2 %0, %1, %2, %0;" : "+l"(acc) : "l"(x), "l"(w))
#define UNPK(v, lo, hi) asm("mov.b64 {%0, %1}, %2;" : "=f"(lo), "=f"(hi) : "l"(v))

// ---------------- prep 1: weights + c2 ------------------------------------
__global__ void prep_w_kernel(const float* __restrict__ ks,
                              const float* __restrict__ kr,
                              const float* __restrict__ kc) {
    int tid = threadIdx.x;
    if (tid < 32) {
        int oi = tid; float s = 0.0f;
        const float* a = ks + oi * 16;
        #pragma unroll
        for (int j = 0; j < 16; j++) s += a[j] * a[j];
        const float* r = kr + oi * 4; const float* c = kc + oi * 4;
        #pragma unroll
        for (int j = 0; j < 4; j++) { s += r[j] * r[j]; s += c[j] * c[j]; }
        g_c2[oi] = s;
    }
    for (int e = tid; e < 32 * 24 * 16; e += blockDim.x) {
        int c = e & 15; int t2 = e >> 4;
        int p = t2 % 24; int oi = t2 / 24;
        int a = c >> 2, bb = c & 3;
        float val = ks[oi * 16 + (int)c_P[p][a] * 4 + (int)c_P[p][bb]];
        g_Wn[(oi * 24 + p) * 16 + c] = -2.0f * val;
    }
}

// ---------------- prep 2: rp/cp tables (scalar-perm, padded h) ------------
__global__ void prep_tab_kernel(const float* __restrict__ types,
                                const float* __restrict__ kr,
                                const float* __restrict__ kc) {
    int idx = blockIdx.x, tid = threadIdx.x;
    int b = idx / NH, h = idx - b * NH;
    for (int e = tid; e < 768; e += blockDim.x) {
        int oi = e / 24, p = e % 24;
        int i = oi & 3;
        const float* tp = types + (b * 4 + i) * 224 + h;
        float t0 = tp[0], t1 = tp[2], t2 = tp[4], t3 = tp[6];
        float t2s = t0 * t0 + t1 * t1 + t2 * t2 + t3 * t3;
        const float* krp = kr + oi * 4;
        const float* kcp = kc + oi * 4;
        float rd = t0 * krp[c_P[p][0]] + t1 * krp[c_P[p][1]] + t2 * krp[c_P[p][2]] + t3 * krp[c_P[p][3]];
        float cd = t0 * kcp[c_P[p][0]] + t1 * kcp[c_P[p][1]] + t2 * kcp[c_P[p][2]] + t3 * kcp[c_P[p][3]];
        size_t lin = ((size_t)(b * 32 + oi) * 24 + p) * NHP + h;
        g_rpn[lin] = t2s - 2.0f * rd;
        g_cpn[lin] = t2s - 2.0f * cd;
    }
}

// ---------------- prep 3: h_mean closed form -------------------------------
__global__ void prep_h_kernel(const float* __restrict__ feats, float* __restrict__ out) {
    int b = blockIdx.x, f = threadIdx.x;
    float acc = 0.0f;
    for (int n = 0; n < 224; n++) {
        int lo = (n >= NH) ? ((n - (NH - 2)) >> 1) : 0;
        int hi = min(3, n >> 1);
        acc += (float)(hi - lo + 1) * feats[(b * 224 + n) * 128 + f];
    }
    out[b * 128 + f] = acc * (2.0f / (float)NH);
}

// ---------------- sims: 4 subwindows packed across f32x2 lanes ------------
// thread = (h1 local row lh, quad-group u): subs h2 = 4u..4u+3
// block = 220 threads = 4 h1 rows; grid = (55, B=2, 4 o-pairs); 8 (i,o) per block
__global__ void __launch_bounds__(TPB, 3)
sims_kernel(const float* __restrict__ graph) {
    __shared__ __align__(16) float sw[8 * 24 * 16];   // 12 KB: [oiL][p][c]
    __shared__ float    srp[4][8][24];                // rpart for 4 h1
    __shared__ float    sc2s[8];
    __shared__ unsigned smaxu[4][8];
    __shared__ float    smaxf[4][8];
    __shared__ float    ssumv[4][8];

    int t  = threadIdx.x;
    int b  = blockIdx.y;
    int zo = blockIdx.z;              // o-pair index: o = zo*2 + oL
    int h1base = blockIdx.x * 4;

    {
        const float4* srcw = (const float4*)(g_Wn + zo * 8 * 384);
        float4* dstw = (float4*)sw;
        for (int e = t; e < 768; e += TPB) dstw[e] = srcw[e];
        for (int e = t; e < 768; e += TPB) {
            int lh = e / 192, r = e % 192, oiL = r / 24, p = r % 24;
            int h1s = min(h1base + lh, NH - 1);
            srp[lh][oiL][p] = g_rpn[((size_t)(b * 32 + zo * 8 + oiL) * 24 + p) * NHP + h1s];
        }
        if (t < 8) sc2s[t] = g_c2[zo * 8 + t];
        if (t < 32) { smaxu[t / 8][t % 8] = 0u; ssumv[t / 8][t % 8] = 0.0f; }
    }
    __syncthreads();

    int lh = t / QG, u = t - lh * QG;
    int h1 = h1base + lh;
    bool h1v = h1 < NH;
    int h1c = h1v ? h1 : NH - 1;
    int h2b = 4 * u;
    int nk = h1v ? ((h2b + 4 <= NH) ? 4 : NH - h2b) : 0;  // 4, 2 (u=54), or 0
    bool fullq = (u < QG - 1);

    #pragma unroll 1
    for (int i = 0; i < 4; i++) {
        unsigned long long xA[16], xB[16];
        float x20 = 0.f, x21 = 0.f, x22 = 0.f, x23 = 0.f;
        const float* gp = graph + (((size_t)(b * 4 + i) * 224) + h1c) * 224 + h2b;
        #pragma unroll
        for (int a = 0; a < 4; a++) {
            #pragma unroll
            for (int bb = 0; bb < 4; bb++) {
                int c = a * 4 + bb;
                const float* ad = gp + (2 * a) * 224 + 2 * bb;
                float2 v01 = *(const float2*)ad;                 // subs 0,1
                float2 v23 = fullq ? *(const float2*)(ad + 2)    // subs 2,3
                                   : make_float2(0.f, 0.f);
                xA[c] = pk2(v01.x, v01.y);
                xB[c] = pk2(v23.x, v23.y);
                x20 = fmaf(v01.x, v01.x, x20);
                x21 = fmaf(v01.y, v01.y, x21);
                x22 = fmaf(v23.x, v23.x, x22);
                x23 = fmaf(v23.y, v23.y, x23);
            }
        }
        unsigned long long b01 = pk2(x20, x21);
        unsigned long long b23 = pk2(x22, x23);

        #pragma unroll 1
        for (int oL = 0; oL < 2; oL++) {
            int oiL = oL * 4 + i;
            const float* wp  = sw + oiL * 384;
            const float* rpp = &srp[lh][oiL][0];
            const float* cpg = g_cpn + ((size_t)(b * 32 + zo * 8 + oiL) * 24) * NHP + h2b;
            float sc2v = sc2s[oiL];
            float m0 = FLT_MAX, m1 = FLT_MAX, m2 = FLT_MAX, m3 = FLT_MAX;
            #pragma unroll 4
            for (int p = 0; p < 24; p++) {
                ulonglong2 cpq = *(const ulonglong2*)(cpg + p * NHP);
                unsigned long long crp2 = dup2(sc2v + rpp[p]);
                unsigned long long a01 = add2(add2(b01, crp2), cpq.x);
                unsigned long long a23 = add2(add2(b23, crp2), cpq.y);
                const float* wq = wp + p * 16;
                #pragma unroll
                for (int c = 0; c < 16; c++) {
                    unsigned long long w2 = dup2(wq[c]);
                    FMA2(a01, xA[c], w2);
                    FMA2(a23, xB[c], w2);
                }
                float d0, d1, d2, d3;
                UNPK(a01, d0, d1); UNPK(a23, d2, d3);
                m0 = fminf(m0, d0); m1 = fminf(m1, d1);
                m2 = fminf(m2, d2); m3 = fminf(m3, d3);
            }
            if (nk) {
                int row = b * 32 + zo * 8 + oiL;
                float* sp = g_sims + (size_t)row * NSUB + h1 * NH + h2b;
                *(float2*)sp = make_float2(m0, m1);
                float tm = fmaxf(m0, m1);
                if (nk == 4) {
                    *(float2*)(sp + 2) = make_float2(m2, m3);
                    tm = fmaxf(tm, fmaxf(m2, m3));
                }
                unsigned uu  = __float_as_uint(tm);
                unsigned key = (uu & 0x80000000u) ? ~uu : (uu | 0x80000000u);
                atomicMax(&smaxu[lh][oiL], key);
            }
        }
    }

    __syncthreads();
    if (t < 32) {
        unsigned uu = smaxu[t / 8][t % 8];
        smaxf[t / 8][t % 8] = (uu & 0x80000000u) ? __uint_as_float(uu & 0x7fffffffu)
                                                 : __uint_as_float(~uu);
    }
    __syncthreads();

    // phase 2: in-place exp (thread re-reads only its own writes)
    if (nk) {
        #pragma unroll 1
        for (int oiL = 0; oiL < 8; oiL++) {
            int row = b * 32 + zo * 8 + oiL;
            float mx = smaxf[lh][oiL];
            float* sp = g_sims + (size_t)row * NSUB + h1 * NH + h2b;
            float2 v01 = *(float2*)sp;
            float e0 = __expf(v01.x - mx), e1 = __expf(v01.y - mx);
            *(float2*)sp = make_float2(e0, e1);
            float ssv = e0 + e1;
            if (nk == 4) {
                float2 v23 = *(float2*)(sp + 2);
                float e2 = __expf(v23.x - mx), e3 = __expf(v23.y - mx);
                *(float2*)(sp + 2) = make_float2(e2, e3);
                ssv += e2 + e3;
            }
            atomicAdd(&ssumv[lh][oiL], ssv);
        }
    }
    __syncthreads();
    if (t < 32) {
        int lh2 = t / 8, oiL = t % 8, h1w = h1base + lh2;
        if (h1w < NH) {
            int row = b * 32 + zo * 8 + oiL;
            g_pmax[row][h1w] = smaxf[lh2][oiL];
            g_psum[row][h1w] = ssumv[lh2][oiL];
        }
    }
}

// ---------------- combine: global max/sum + factor table -------------------
__global__ void combine_kernel() {
    __shared__ float red[256];
    int row = blockIdx.x, tid = threadIdx.x;
    float pm = (tid < NH) ? g_pmax[row][tid] : -FLT_MAX;
    red[tid] = pm; __syncthreads();
    #pragma unroll
    for (int st = 128; st; st >>= 1) {
        if (tid < st) red[tid] = fmaxf(red[tid], red[tid + st]);
        __syncthreads();
    }
    float gmx = red[0];
    __syncthreads();
    float ex = (tid < NH) ? __expf(pm - gmx) : 0.0f;
    red[tid] = (tid < NH) ? g_psum[row][tid] * ex : 0.0f;
    __syncthreads();
    #pragma unroll
    for (int st = 128; st; st >>= 1) {
        if (tid < st) red[tid] += red[tid + st];
        __syncthreads();
    }
    float S = red[0];
    if (tid < NH) g_fac[row][tid] = ex / S;
}

// ---------------- writeout: pure streaming multiply ------------------------
__global__ void writeout_kernel(float* __restrict__ out) {
    int h1 = blockIdx.x, row = blockIdx.y, tid = threadIdx.x;
    if (tid >= NH) return;
    float f = g_fac[row][h1];
    size_t idx = (size_t)row * NSUB + h1 * NH + tid;
    float e = g_sims[idx];
    out[256 + idx] = (1.0f - e * f) * (1.0f / (float)NSUB);
}

// ---------------- launch ---------------------------------------------------
extern "C" void kernel_launch(void* const* d_in, const int* in_sizes, int n_in,
                              void* d_out, int out_size) {
    const float* graph    = (const float*)d_in[0];
    const float* types    = (const float*)d_in[1];
    const float* features = (const float*)d_in[2];
    const float* ks       = (const float*)d_in[3];
    const float* kr       = (const float*)d_in[4];
    const float* kc       = (const float*)d_in[5];
    float* out = (float*)d_out;

    prep_w_kernel<<<1, 256>>>(ks, kr, kc);
    prep_tab_kernel<<<2 * NH, 256>>>(types, kr, kc);
    prep_h_kernel<<<2, 128>>>(features, out);
    sims_kernel<<<dim3(QG, 2, 4), TPB>>>(graph);      // launch #4 -> ncu capture
    combine_kernel<<<NROWS, 256>>>();
    writeout_kernel<<<dim3(NH, NROWS), 224>>>(out);
}

// round 7
// speedup vs baseline: 1.4866x; 1.4866x over previous
#include <cuda_runtime.h>
#include <cstdint>
#include <cfloat>

#define NH    218
#define NHP   224        // padded h stride (16B-aligned rows)
#define NSUB  47524      // 218*218
#define NROWS 64         // B * C_OUT * C_IN
#define QG    55         // quad-groups per h1 row (55*4 = 220 >= 218)
#define TPB   220        // 4 h1 rows * 55 quad-groups

// ---------------- device globals (no allocations allowed) ----------------
__device__ __align__(16) float g_Wn[32 * 24 * 16];          // -2*Kstruct, [oi][p][c]
__device__ float g_c2[32];                                   // ||K||^2+||R||^2+||C||^2
__device__ __align__(16) float g_rpn[2 * 32 * 24 * NHP];     // rpart [b][oi][p][h1]
__device__ __align__(16) float g_cpn[2 * 32 * 24 * NHP];     // cpart [b][oi][p][h2]
__device__ float g_pmax[NROWS][NH];
__device__ float g_psum[NROWS][NH];
__device__ float g_fac[NROWS][NH];
__device__ __align__(16) float g_sims[(size_t)NROWS * NSUB]; // m, then exp(m - blkmax)

__constant__ unsigned char c_P[24][4] = {
  {0,1,2,3},{0,1,3,2},{0,2,1,3},{0,2,3,1},{0,3,1,2},{0,3,2,1},
  {1,0,2,3},{1,0,3,2},{1,2,0,3},{1,2,3,0},{1,3,0,2},{1,3,2,0},
  {2,0,1,3},{2,0,3,1},{2,1,0,3},{2,1,3,0},{2,3,0,1},{2,3,1,0},
  {3,0,1,2},{3,0,2,1},{3,1,0,2},{3,1,2,0},{3,2,0,1},{3,2,1,0}
};

// ---------------- packed f32x2 helpers -----------------------------------
__device__ __forceinline__ unsigned long long dup2(float f) {
    unsigned long long r;
    asm("mov.b64 %0, {%1, %1};" : "=l"(r) : "f"(f));
    return r;
}
__device__ __forceinline__ unsigned long long pk2(float a, float b) {
    unsigned long long r;
    asm("mov.b64 %0, {%1, %2};" : "=l"(r) : "f"(a), "f"(b));
    return r;
}
__device__ __forceinline__ unsigned long long add2(unsigned long long a, unsigned long long b) {
    unsigned long long r;
    asm("add.rn.f32x2 %0, %1, %2;" : "=l"(r) : "l"(a), "l"(b));
    return r;
}
#define FMA2(acc, x, w) asm("fma.rn.f32x2 %0, %1, %2, %0;" : "+l"(acc) : "l"(x), "l"(w))
#define UNPK(v, lo, hi) asm("mov.b64 {%0, %1}, %2;" : "=f"(lo), "=f"(hi) : "l"(v))

// ---------------- prep 1: weights + c2 ------------------------------------
__global__ void prep_w_kernel(const float* __restrict__ ks,
                              const float* __restrict__ kr,
                              const float* __restrict__ kc) {
    int tid = threadIdx.x;
    if (tid < 32) {
        int oi = tid; float s = 0.0f;
        const float* a = ks + oi * 16;
        #pragma unroll
        for (int j = 0; j < 16; j++) s += a[j] * a[j];
        const float* r = kr + oi * 4; const float* c = kc + oi * 4;
        #pragma unroll
        for (int j = 0; j < 4; j++) { s += r[j] * r[j]; s += c[j] * c[j]; }
        g_c2[oi] = s;
    }
    for (int e = tid; e < 32 * 24 * 16; e += blockDim.x) {
        int c = e & 15; int t2 = e >> 4;
        int p = t2 % 24; int oi = t2 / 24;
        int a = c >> 2, bb = c & 3;
        float val = ks[oi * 16 + (int)c_P[p][a] * 4 + (int)c_P[p][bb]];
        g_Wn[(oi * 24 + p) * 16 + c] = -2.0f * val;
    }
}

// ---------------- prep 2: rp/cp tables (scalar-perm, padded h) ------------
__global__ void prep_tab_kernel(const float* __restrict__ types,
                                const float* __restrict__ kr,
                                const float* __restrict__ kc) {
    int idx = blockIdx.x, tid = threadIdx.x;
    int b = idx / NH, h = idx - b * NH;
    for (int e = tid; e < 768; e += blockDim.x) {
        int oi = e / 24, p = e % 24;
        int i = oi & 3;
        const float* tp = types + (b * 4 + i) * 224 + h;
        float t0 = tp[0], t1 = tp[2], t2 = tp[4], t3 = tp[6];
        float t2s = t0 * t0 + t1 * t1 + t2 * t2 + t3 * t3;
        const float* krp = kr + oi * 4;
        const float* kcp = kc + oi * 4;
        float rd = t0 * krp[c_P[p][0]] + t1 * krp[c_P[p][1]] + t2 * krp[c_P[p][2]] + t3 * krp[c_P[p][3]];
        float cd = t0 * kcp[c_P[p][0]] + t1 * kcp[c_P[p][1]] + t2 * kcp[c_P[p][2]] + t3 * kcp[c_P[p][3]];
        size_t lin = ((size_t)(b * 32 + oi) * 24 + p) * NHP + h;
        g_rpn[lin] = t2s - 2.0f * rd;
        g_cpn[lin] = t2s - 2.0f * cd;
    }
}

// ---------------- prep 3: h_mean closed form -------------------------------
__global__ void prep_h_kernel(const float* __restrict__ feats, float* __restrict__ out) {
    int b = blockIdx.x, f = threadIdx.x;
    float acc = 0.0f;
    for (int n = 0; n < 224; n++) {
        int lo = (n >= NH) ? ((n - (NH - 2)) >> 1) : 0;
        int hi = min(3, n >> 1);
        acc += (float)(hi - lo + 1) * feats[(b * 224 + n) * 128 + f];
    }
    out[b * 128 + f] = acc * (2.0f / (float)NH);
}

// ---------------- sims: 4 subwindows packed across f32x2 lanes ------------
// Overlap trick: quad at h2b needs graph cols h2b..h2b+9 per row a — 5 packed
// pairs xq[a][0..4]; sub-pair (0,1) comp bb uses xq[a][bb], sub-pair (2,3)
// uses xq[a][bb+1]. x storage: 40 regs (was 128 -> spilled in R6).
__global__ void __launch_bounds__(TPB, 3)
sims_kernel(const float* __restrict__ graph) {
    __shared__ __align__(16) float sw[8 * 24 * 16];   // 12 KB: [oiL][p][c]
    __shared__ float    srp[4][8][24];                // rpart for 4 h1
    __shared__ float    sc2s[8];
    __shared__ unsigned smaxu[4][8];
    __shared__ float    smaxf[4][8];
    __shared__ float    ssumv[4][8];

    int t  = threadIdx.x;
    int b  = blockIdx.y;
    int zo = blockIdx.z;              // o-pair index: o = zo*2 + oL
    int h1base = blockIdx.x * 4;

    {
        const float4* srcw = (const float4*)(g_Wn + zo * 8 * 384);
        float4* dstw = (float4*)sw;
        for (int e = t; e < 768; e += TPB) dstw[e] = srcw[e];
        for (int e = t; e < 768; e += TPB) {
            int lh = e / 192, r = e % 192, oiL = r / 24, p = r % 24;
            int h1s = min(h1base + lh, NH - 1);
            srp[lh][oiL][p] = g_rpn[((size_t)(b * 32 + zo * 8 + oiL) * 24 + p) * NHP + h1s];
        }
        if (t < 8) sc2s[t] = g_c2[zo * 8 + t];
        if (t < 32) { smaxu[t / 8][t % 8] = 0u; ssumv[t / 8][t % 8] = 0.0f; }
    }
    __syncthreads();

    int lh = t / QG, u = t - lh * QG;
    int h1 = h1base + lh;
    bool h1v = h1 < NH;
    int h1c = h1v ? h1 : NH - 1;
    int h2b = 4 * u;
    int nk = h1v ? ((h2b + 4 <= NH) ? 4 : NH - h2b) : 0;  // 4, 2 (u=54), or 0
    bool fullq = (u < QG - 1);

    #pragma unroll 1
    for (int i = 0; i < 4; i++) {
        unsigned long long xq[4][5];
        float x20 = 0.f, x21 = 0.f, x22 = 0.f, x23 = 0.f;
        const float* gp = graph + (((size_t)(b * 4 + i) * 224) + h1c) * 224 + h2b;
        #pragma unroll
        for (int a = 0; a < 4; a++) {
            const float* ad = gp + (2 * a) * 224;
            float4 v0 = *(const float4*)ad;          // g0..g3
            float4 v1 = *(const float4*)(ad + 4);    // g4..g7
            float2 v2 = fullq ? *(const float2*)(ad + 8) : make_float2(0.f, 0.f);
            xq[a][0] = pk2(v0.x, v0.y);
            xq[a][1] = pk2(v0.z, v0.w);
            xq[a][2] = pk2(v1.x, v1.y);
            xq[a][3] = pk2(v1.z, v1.w);
            xq[a][4] = pk2(v2.x, v2.y);
            x20 = fmaf(v0.x, v0.x, fmaf(v0.z, v0.z, fmaf(v1.x, v1.x, fmaf(v1.z, v1.z, x20))));
            x21 = fmaf(v0.y, v0.y, fmaf(v0.w, v0.w, fmaf(v1.y, v1.y, fmaf(v1.w, v1.w, x21))));
            x22 = fmaf(v0.z, v0.z, fmaf(v1.x, v1.x, fmaf(v1.z, v1.z, fmaf(v2.x, v2.x, x22))));
            x23 = fmaf(v0.w, v0.w, fmaf(v1.y, v1.y, fmaf(v1.w, v1.w, fmaf(v2.y, v2.y, x23))));
        }
        unsigned long long b01 = pk2(x20, x21);
        unsigned long long b23 = pk2(x22, x23);

        #pragma unroll 1
        for (int oL = 0; oL < 2; oL++) {
            int oiL = oL * 4 + i;
            const float* wp  = sw + oiL * 384;
            const float* rpp = &srp[lh][oiL][0];
            const float* cpg = g_cpn + ((size_t)(b * 32 + zo * 8 + oiL) * 24) * NHP + h2b;
            float sc2v = sc2s[oiL];
            float m0 = FLT_MAX, m1 = FLT_MAX, m2 = FLT_MAX, m3 = FLT_MAX;
            #pragma unroll 4
            for (int p = 0; p < 24; p++) {
                ulonglong2 cpq = *(const ulonglong2*)(cpg + p * NHP);
                unsigned long long crp2 = dup2(sc2v + rpp[p]);
                unsigned long long a01 = add2(add2(b01, crp2), cpq.x);
                unsigned long long a23 = add2(add2(b23, crp2), cpq.y);
                const float* wq = wp + p * 16;
                #pragma unroll
                for (int a = 0; a < 4; a++) {
                    #pragma unroll
                    for (int bb = 0; bb < 4; bb++) {
                        unsigned long long w2 = dup2(wq[a * 4 + bb]);
                        FMA2(a01, xq[a][bb],     w2);
                        FMA2(a23, xq[a][bb + 1], w2);
                    }
                }
                float d0, d1, d2, d3;
                UNPK(a01, d0, d1); UNPK(a23, d2, d3);
                m0 = fminf(m0, d0); m1 = fminf(m1, d1);
                m2 = fminf(m2, d2); m3 = fminf(m3, d3);
            }
            if (nk) {
                int row = b * 32 + zo * 8 + oiL;
                float* sp = g_sims + (size_t)row * NSUB + h1 * NH + h2b;
                *(float2*)sp = make_float2(m0, m1);
                float tm = fmaxf(m0, m1);
                if (nk == 4) {
                    *(float2*)(sp + 2) = make_float2(m2, m3);
                    tm = fmaxf(tm, fmaxf(m2, m3));
                }
                unsigned uu  = __float_as_uint(tm);
                unsigned key = (uu & 0x80000000u) ? ~uu : (uu | 0x80000000u);
                atomicMax(&smaxu[lh][oiL], key);
            }
        }
    }

    __syncthreads();
    if (t < 32) {
        unsigned uu = smaxu[t / 8][t % 8];
        smaxf[t / 8][t % 8] = (uu & 0x80000000u) ? __uint_as_float(uu & 0x7fffffffu)
                                                 : __uint_as_float(~uu);
    }
    __syncthreads();

    // phase 2: in-place exp (thread re-reads only its own writes)
    if (nk) {
        #pragma unroll 1
        for (int oiL = 0; oiL < 8; oiL++) {
            int row = b * 32 + zo * 8 + oiL;
            float mx = smaxf[lh][oiL];
            float* sp = g_sims + (size_t)row * NSUB + h1 * NH + h2b;
            float2 v01 = *(float2*)sp;
            float e0 = __expf(v01.x - mx), e1 = __expf(v01.y - mx);
            *(float2*)sp = make_float2(e0, e1);
            float ssv = e0 + e1;
            if (nk == 4) {
                float2 v23 = *(float2*)(sp + 2);
                float e2 = __expf(v23.x - mx), e3 = __expf(v23.y - mx);
                *(float2*)(sp + 2) = make_float2(e2, e3);
                ssv += e2 + e3;
            }
            atomicAdd(&ssumv[lh][oiL], ssv);
        }
    }
    __syncthreads();
    if (t < 32) {
        int lh2 = t / 8, oiL = t % 8, h1w = h1base + lh2;
        if (h1w < NH) {
            int row = b * 32 + zo * 8 + oiL;
            g_pmax[row][h1w] = smaxf[lh2][oiL];
            g_psum[row][h1w] = ssumv[lh2][oiL];
        }
    }
}

// ---------------- combine: global max/sum + factor table -------------------
__global__ void combine_kernel() {
    __shared__ float red[256];
    int row = blockIdx.x, tid = threadIdx.x;
    float pm = (tid < NH) ? g_pmax[row][tid] : -FLT_MAX;
    red[tid] = pm; __syncthreads();
    #pragma unroll
    for (int st = 128; st; st >>= 1) {
        if (tid < st) red[tid] = fmaxf(red[tid], red[tid + st]);
        __syncthreads();
    }
    float gmx = red[0];
    __syncthreads();
    float ex = (tid < NH) ? __expf(pm - gmx) : 0.0f;
    red[tid] = (tid < NH) ? g_psum[row][tid] * ex : 0.0f;
    __syncthreads();
    #pragma unroll
    for (int st = 128; st; st >>= 1) {
        if (tid < st) red[tid] += red[tid + st];
        __syncthreads();
    }
    float S = red[0];
    if (tid < NH) g_fac[row][tid] = ex / S;
}

// ---------------- writeout: pure streaming multiply ------------------------
__global__ void writeout_kernel(float* __restrict__ out) {
    int h1 = blockIdx.x, row = blockIdx.y, tid = threadIdx.x;
    if (tid >= NH) return;
    float f = g_fac[row][h1];
    size_t idx = (size_t)row * NSUB + h1 * NH + tid;
    float e = g_sims[idx];
    out[256 + idx] = (1.0f - e * f) * (1.0f / (float)NSUB);
}

// ---------------- launch ---------------------------------------------------
extern "C" void kernel_launch(void* const* d_in, const int* in_sizes, int n_in,
                              void* d_out, int out_size) {
    const float* graph    = (const float*)d_in[0];
    const float* types    = (const float*)d_in[1];
    const float* features = (const float*)d_in[2];
    const float* ks       = (const float*)d_in[3];
    const float* kr       = (const float*)d_in[4];
    const float* kc       = (const float*)d_in[5];
    float* out = (float*)d_out;

    prep_w_kernel<<<1, 256>>>(ks, kr, kc);
    prep_tab_kernel<<<2 * NH, 256>>>(types, kr, kc);
    prep_h_kernel<<<2, 128>>>(features, out);
    sims_kernel<<<dim3(QG, 2, 4), TPB>>>(graph);      // launch #4 -> ncu capture
    combine_kernel<<<NROWS, 256>>>();
    writeout_kernel<<<dim3(NH, NROWS), 224>>>(out);
}